// round 13
// baseline (speedup 1.0000x reference)
#include <cuda_runtime.h>
#include <cuda_fp16.h>
#include <mma.h>
#include <cstdint>

using namespace nvcuda;

// ---------------- problem constants ----------------
#define BATCH   16
#define DIM     256
#define HEADS   8
#define DHEAD   32
#define NPIX    4096
#define SCALE   0.17677669529663687f
#define EPS     1e-5f

// ---------------- scratch ----------------
__device__ __half g_xnh [(size_t)BATCH * NPIX * DIM];   // pixel-major fp16: LN out, later attn out
__device__ __half g_qkv [(size_t)BATCH * 768 * NPIX];   // q,k,v after 1x1, fp16 channel-major
__device__ __half g_kv  [(size_t)BATCH * 512 * NPIX];   // k(softmaxed),v after dwconv, fp16
__device__ float  g_ctxp[(size_t)BATCH * HEADS * 4 * DHEAD * DHEAD];  // 4 pixel-slice partials
__device__ __half g_wqkv[768 * 256];
__device__ __half g_wo2 [256 * 256];

__device__ __forceinline__ void cp16s(void* dst, const void* src) {
    unsigned d = (unsigned)__cvta_generic_to_shared(dst);
    asm volatile("cp.async.cg.shared.global [%0], [%1], 16;\n" :: "r"(d), "l"(src));
}
#define CP_COMMIT()  asm volatile("cp.async.commit_group;\n" ::: "memory")
#define CP_WAIT0()   asm volatile("cp.async.wait_group 0;\n" ::: "memory")
#define CP_WAIT1()   asm volatile("cp.async.wait_group 1;\n" ::: "memory")

// =====================================================================
// 0a/0b. weights -> fp16 (split into two launches so gemm_qkv is the
//        4th launch — ncu's -s5-c1 capture lands on it)
// =====================================================================
__global__ __launch_bounds__(256)
void round_weights_qkv(const float* __restrict__ wq, const float* __restrict__ wk,
                       const float* __restrict__ wv)
{
    int i = blockIdx.x * 256 + threadIdx.x;     // 768 blocks -> 196608
    if (i < 65536)       g_wqkv[i] = __float2half_rn(wq[i]);
    else if (i < 131072) g_wqkv[i] = __float2half_rn(wk[i - 65536]);
    else                 g_wqkv[i] = __float2half_rn(wv[i - 131072]);
}

__global__ __launch_bounds__(256)
void round_weights_wo(const float* __restrict__ wo)
{
    int i = blockIdx.x * 256 + threadIdx.x;     // 256 blocks -> 65536
    g_wo2[i] = __float2half_rn(wo[i]);
}

// =====================================================================
// 1. channel LayerNorm: channel-major fp32 in -> pixel-major fp16 out
// =====================================================================
__global__ __launch_bounds__(256)
void ln_to_pix(const float* __restrict__ in, const float* __restrict__ g,
               __half* __restrict__ out)
{
    int idx = blockIdx.x * 256 + threadIdx.x;
    int b = idx >> 12, p = idx & 4095;
    const float* base = in + (size_t)b * DIM * NPIX + p;

    float s = 0.f, ss = 0.f;
#pragma unroll 8
    for (int c = 0; c < DIM; c++) {
        float v = base[(size_t)c * NPIX];
        s += v; ss += v * v;
    }
    float mean = s * (1.f / DIM);
    float var  = ss * (1.f / DIM) - mean * mean;
    float rstd = rsqrtf(var + EPS);

    __half* orow = out + ((size_t)b * NPIX + p) * DIM;
#pragma unroll 4
    for (int c = 0; c < DIM; c += 8) {
        __half2 h[4];
#pragma unroll
        for (int j = 0; j < 4; j++) {
            float a = (base[(size_t)(c + 2*j)     * NPIX] - mean) * rstd * __ldg(&g[c + 2*j]);
            float bb= (base[(size_t)(c + 2*j + 1) * NPIX] - mean) * rstd * __ldg(&g[c + 2*j + 1]);
            h[j] = __floats2half2_rn(a, bb);
        }
        *reinterpret_cast<uint4*>(orow + c) = *reinterpret_cast<uint4*>(h);
    }
}

// =====================================================================
// 2. QKV fp16 WMMA GEMM, 3-stage cp.async pipeline, fp16 outputs.
// =====================================================================
#define BM 128
#define BN 128
#define BKH 32
#define LDH (BKH + 8)
#define STG_LD 20
#define QKV_DYN (3 * (BM * LDH + BN * LDH) * 2)   /* 61440 B */

__global__ __launch_bounds__(512)
void gemm_qkv(const __half* __restrict__ A, const __half* __restrict__ B,
              __half* __restrict__ C)
{
    extern __shared__ char gsm[];
    typedef __half AsT[BM][LDH];
    typedef __half BsT[BN][LDH];
    AsT* As = reinterpret_cast<AsT*>(gsm);                          // As[3]
    BsT* Bs = reinterpret_cast<BsT*>(gsm + 3 * BM * LDH * 2);       // Bs[3]

    const int tid = threadIdx.x;
    const int bm = blockIdx.y * BM;
    const int bn = blockIdx.x * BN;
    const int z  = blockIdx.z;
    const __half* Bb = B + (size_t)z * NPIX * DIM;

    const int warp = tid >> 5;
    const int wm = (warp >> 2) * 32;
    const int wn = (warp & 3) * 32;

    const int row  = tid >> 2;
    const int col8 = (tid & 3) * 8;
    const __half* gA = &A[(size_t)(bm + row) * 256 + col8];
    const __half* gB = &Bb[(size_t)(bn + row) * 256 + col8];

    wmma::fragment<wmma::accumulator, 16, 16, 16, float> acc[2][2];
#pragma unroll
    for (int i = 0; i < 2; i++)
#pragma unroll
        for (int j = 0; j < 2; j++) wmma::fill_fragment(acc[i][j], 0.f);

    // prologue: chunks 0,1 into stages 0,1
#pragma unroll
    for (int c = 0; c < 2; c++) {
        cp16s(&As[c][row][col8], gA + c * BKH);
        cp16s(&Bs[c][row][col8], gB + c * BKH);
        CP_COMMIT();
    }

#pragma unroll 1
    for (int t = 0; t < 8; t++) {
        if (t < 7) { CP_WAIT1(); } else { CP_WAIT0(); }
        __syncthreads();
        if (t + 2 < 8) {
            int s = (t + 2) % 3;
            cp16s(&As[s][row][col8], gA + (t + 2) * BKH);
            cp16s(&Bs[s][row][col8], gB + (t + 2) * BKH);
            CP_COMMIT();
        }
        int cs_ = t % 3;
#pragma unroll
        for (int kk = 0; kk < BKH; kk += 16) {
            wmma::fragment<wmma::matrix_a, 16, 16, 16, __half, wmma::row_major> af[2];
            wmma::fragment<wmma::matrix_b, 16, 16, 16, __half, wmma::col_major> bf[2];
#pragma unroll
            for (int i = 0; i < 2; i++)
                wmma::load_matrix_sync(af[i], &As[cs_][wm + i * 16][kk], LDH);
#pragma unroll
            for (int j = 0; j < 2; j++)
                wmma::load_matrix_sync(bf[j], &Bs[cs_][wn + j * 16][kk], LDH);
#pragma unroll
            for (int i = 0; i < 2; i++)
#pragma unroll
                for (int j = 0; j < 2; j++)
                    wmma::mma_sync(acc[i][j], af[i], bf[j], acc[i][j]);
        }
    }

    // fp16 epilogue via per-warp staging (reuse pipeline smem)
    __syncthreads();
    float* stg = reinterpret_cast<float*>(gsm) + warp * 16 * STG_LD;
    __half* Ch = C + (size_t)z * 768 * NPIX + (size_t)bm * NPIX;
    const int lane = tid & 31;
    const int r  = lane >> 1;
    const int c8 = (lane & 1) * 8;
#pragma unroll
    for (int i = 0; i < 2; i++)
#pragma unroll
        for (int j = 0; j < 2; j++) {
            wmma::store_matrix_sync(stg, acc[i][j], STG_LD, wmma::mem_row_major);
            __syncwarp();
            const float* src = stg + r * STG_LD + c8;
            __half2 hh[4];
#pragma unroll
            for (int q = 0; q < 4; q++)
                hh[q] = __floats2half2_rn(src[2*q], src[2*q + 1]);
            __half* dst = Ch + (size_t)(wm + i * 16 + r) * NPIX
                             + bn + wn + j * 16 + c8;
            *reinterpret_cast<uint4*>(dst) = *reinterpret_cast<uint4*>(hh);
            __syncwarp();
        }
}

// =====================================================================
// 3. depthwise 3x3 for k,v — fp16 end-to-end (proven round 12).
// =====================================================================
#define KVLD 80

__global__ __launch_bounds__(256)
void dwconv_kv(const __half* __restrict__ qkv, const float* __restrict__ wk,
               const float* __restrict__ wv, __half* __restrict__ kvout)
{
    __shared__ __half s[66 * KVLD];
    __shared__ float red[8];
    int bc = blockIdx.x;                  // b*512 + ch
    int b = bc >> 9;
    int ch = bc & 511;
    bool is_k = ch < 256;
    const float* w9 = is_k ? wk + ch * 9 : wv + (ch - 256) * 9;
    float w0 = w9[0], w1 = w9[1], w2 = w9[2], w3 = w9[3], w4 = w9[4],
          w5 = w9[5], w6 = w9[6], w7 = w9[7], w8 = w9[8];

    const __half* ip = qkv + ((size_t)b * 768 + 256 + ch) * NPIX;
    __half*       op = kvout + ((size_t)b * 512 + ch) * NPIX;

    int tid = threadIdx.x;
    if (tid < 66) {
        s[7 + tid] = __ushort_as_half(0);
        s[65 * KVLD + 7 + tid] = __ushort_as_half(0);
    }
    if (tid < 64) {
        s[(tid + 1) * KVLD + 7]  = __ushort_as_half(0);
        s[(tid + 1) * KVLD + 72] = __ushort_as_half(0);
    }
    __syncthreads();

    const uint2* ip2 = reinterpret_cast<const uint2*>(ip);
#pragma unroll
    for (int t = 0; t < 4; t++) {
        int i = tid + t * 256;
        int x = i >> 4, y4 = (i & 15) << 2;
        *reinterpret_cast<uint2*>(&s[(x + 1) * KVLD + 8 + y4]) = ip2[i];
    }
    __syncthreads();

    float4 r4[4];
#pragma unroll
    for (int t = 0; t < 4; t++) {
        int i = tid + t * 256;
        int x = i >> 4, y4 = (i & 15) << 2;
        const __half* p = &s[(x + 1) * KVLD + 8 + y4];
        float4 a = make_float4(0.f, 0.f, 0.f, 0.f);
#pragma unroll
        for (int rr = 0; rr < 3; rr++) {
            const __half* q = p + (rr - 1) * KVLD;
            float l  = __half2float(q[-1]);
            float m0 = __half2float(q[0]);
            float m1 = __half2float(q[1]);
            float m2 = __half2float(q[2]);
            float m3 = __half2float(q[3]);
            float rt = __half2float(q[4]);
            float wl = (rr == 0) ? w0 : (rr == 1) ? w3 : w6;
            float wc = (rr == 0) ? w1 : (rr == 1) ? w4 : w7;
            float wr = (rr == 0) ? w2 : (rr == 1) ? w5 : w8;
            a.x += l  * wl + m0 * wc + m1 * wr;
            a.y += m0 * wl + m1 * wc + m2 * wr;
            a.z += m1 * wl + m2 * wc + m3 * wr;
            a.w += m2 * wl + m3 * wc + rt * wr;
        }
        r4[t] = a;
    }

    uint2* op2 = reinterpret_cast<uint2*>(op);
    if (!is_k) {
#pragma unroll
        for (int t = 0; t < 4; t++) {
            uint2 raw;
            __half2* hp = reinterpret_cast<__half2*>(&raw);
            hp[0] = __floats2half2_rn(r4[t].x, r4[t].y);
            hp[1] = __floats2half2_rn(r4[t].z, r4[t].w);
            op2[tid + t * 256] = raw;
        }
        return;
    }

    float m = -1e30f;
#pragma unroll
    for (int t = 0; t < 4; t++)
        m = fmaxf(m, fmaxf(fmaxf(r4[t].x, r4[t].y), fmaxf(r4[t].z, r4[t].w)));
#pragma unroll
    for (int o = 16; o; o >>= 1) m = fmaxf(m, __shfl_xor_sync(~0u, m, o));
    if ((tid & 31) == 0) red[tid >> 5] = m;
    __syncthreads();
    m = red[0];
#pragma unroll
    for (int w = 1; w < 8; w++) m = fmaxf(m, red[w]);

    float ssum = 0.f;
#pragma unroll
    for (int t = 0; t < 4; t++) {
        r4[t].x = __expf(r4[t].x - m); ssum += r4[t].x;
        r4[t].y = __expf(r4[t].y - m); ssum += r4[t].y;
        r4[t].z = __expf(r4[t].z - m); ssum += r4[t].z;
        r4[t].w = __expf(r4[t].w - m); ssum += r4[t].w;
    }
#pragma unroll
    for (int o = 16; o; o >>= 1) ssum += __shfl_xor_sync(~0u, ssum, o);
    __syncthreads();
    if ((tid & 31) == 0) red[tid >> 5] = ssum;
    __syncthreads();
    ssum = 0.f;
#pragma unroll
    for (int w = 0; w < 8; w++) ssum += red[w];

    float inv = 1.f / ssum;
#pragma unroll
    for (int t = 0; t < 4; t++) {
        uint2 raw;
        __half2* hp = reinterpret_cast<__half2*>(&raw);
        hp[0] = __floats2half2_rn(r4[t].x * inv, r4[t].y * inv);
        hp[1] = __floats2half2_rn(r4[t].z * inv, r4[t].w * inv);
        op2[tid + t * 256] = raw;
    }
}

// =====================================================================
// 4. partial ctx: ctxp[bh][s][d][e] = sum_{p in slice} k*v (fp16 in)
// =====================================================================
__global__ __launch_bounds__(256)
void ctx_part(const __half* __restrict__ kv, float* __restrict__ ctxp)
{
    __shared__ float sh[8448];
    float* ksT = sh;
    float* vsT = sh + 4224;

    int bh = blockIdx.x;
    int sl = blockIdx.y;
    int b = bh >> 3, h = bh & 7;
    const __half* kb = kv + ((size_t)b * 512 + h * DHEAD) * NPIX;
    const __half* vb = kv + ((size_t)b * 512 + 256 + h * DHEAD) * NPIX;

    int tid = threadIdx.x;
    int pg = tid >> 6;
    int t  = tid & 63;
    int d0 = (t >> 3) * 4;
    int e0 = (t & 7) * 4;

    float acc[16];
#pragma unroll
    for (int i = 0; i < 16; i++) acc[i] = 0.f;

    int base = sl * 1024;
    for (int c0 = base; c0 < base + 1024; c0 += 128) {
        __syncthreads();
        for (int i = tid; i < 2048; i += 256) {
            int d = i >> 6, p2 = (i & 63) * 2;
            __half2 kk = *reinterpret_cast<const __half2*>(&kb[(size_t)d * NPIX + c0 + p2]);
            __half2 vv = *reinterpret_cast<const __half2*>(&vb[(size_t)d * NPIX + c0 + p2]);
            float2 kf = __half22float2(kk);
            float2 vf = __half22float2(vv);
            ksT[(p2 + 0) * 33 + d] = kf.x;
            ksT[(p2 + 1) * 33 + d] = kf.y;
            vsT[(p2 + 0) * 33 + d] = vf.x;
            vsT[(p2 + 1) * 33 + d] = vf.y;
        }
        __syncthreads();
        int pbeg = pg * 32;
#pragma unroll 4
        for (int pp = pbeg; pp < pbeg + 32; pp++) {
            float kk[4], vv[4];
#pragma unroll
            for (int i = 0; i < 4; i++) kk[i] = ksT[pp * 33 + d0 + i];
#pragma unroll
            for (int j = 0; j < 4; j++) vv[j] = vsT[pp * 33 + e0 + j];
#pragma unroll
            for (int i = 0; i < 4; i++)
#pragma unroll
                for (int j = 0; j < 4; j++) acc[i * 4 + j] += kk[i] * vv[j];
        }
    }
    __syncthreads();

    float* red = sh;
#pragma unroll
    for (int i = 0; i < 4; i++)
#pragma unroll
        for (int j = 0; j < 4; j++)
            red[pg * 1024 + (d0 + i) * 32 + (e0 + j)] = acc[i * 4 + j];
    __syncthreads();

    float* cout = ctxp + ((size_t)bh * 4 + sl) * 1024;
    for (int i = tid; i < 1024; i += 256)
        cout[i] = red[i] + red[1024 + i] + red[2048 + i] + red[3072 + i];
}

// =====================================================================
// 5. FUSED q path: dwconv3x3(q fp16) + feature-softmax + q@ctx + SiLU.
// =====================================================================
#define AF_SQIN_H  (32 * 6 * 80)
#define AF_SQOUT_H (256 * 36)
#define AF_DYN   ((AF_SQIN_H + AF_SQOUT_H) * 2)

__global__ __launch_bounds__(256)
void attn_fused(const __half* __restrict__ qkv, const float* __restrict__ wqdw,
                const float* __restrict__ ctxp, __half* __restrict__ out)
{
    extern __shared__ __half afsm[];
    __half* sq_in  = afsm;
    __half* sq_out = afsm + AF_SQIN_H;
    __shared__ float cs[DHEAD][DHEAD + 1];
    __shared__ float wsm[32][9];

    int blk = blockIdx.x;
    int pt = blk & 15;
    int bh = blk >> 4;
    int b = bh >> 3, h = bh & 7;
    int R0 = pt * 4;
    int tid = threadIdx.x;

    for (int i = tid; i < 288; i += 256)
        wsm[i / 9][i % 9] = wqdw[h * 288 + i];

    const uint2* qin2 = reinterpret_cast<const uint2*>(
        qkv + ((size_t)b * 768 + h * 32) * NPIX);
#pragma unroll
    for (int j = 0; j < 12; j++) {
        int i = tid + j * 256;
        int chl = i / 96;
        int rem = i - chl * 96;
        int rr = rem >> 4, g = rem & 15;
        int x = R0 - 1 + rr;
        uint2 raw = make_uint2(0u, 0u);
        if (x >= 0 && x < 64)
            raw = qin2[(size_t)chl * 1024 + x * 16 + g];
        *reinterpret_cast<uint2*>(&sq_in[(chl * 6 + rr) * 80 + 8 + g * 4]) = raw;
    }
    if (tid < 192) {
        sq_in[tid * 80 + 7]  = __ushort_as_half(0);
        sq_in[tid * 80 + 72] = __ushort_as_half(0);
    }

    const float* cbase = ctxp + (size_t)bh * 4096;
    for (int i = tid; i < 1024; i += 256)
        cs[i >> 5][i & 31] = cbase[i] + cbase[1024 + i] + cbase[2048 + i] + cbase[3072 + i];
    __syncthreads();

#pragma unroll
    for (int t = 0; t < 8; t++) {
        int w = tid + t * 256;
        int ch = w >> 6;
        int rem = w & 63;
        int px = rem >> 4, g = rem & 15;
        const float* wp = wsm[ch];
        float4 a = make_float4(0.f, 0.f, 0.f, 0.f);
#pragma unroll
        for (int rr = 0; rr < 3; rr++) {
            const __half* q = &sq_in[(ch * 6 + px + rr) * 80 + 8 + g * 4];
            float l  = __half2float(q[-1]);
            float m0 = __half2float(q[0]);
            float m1 = __half2float(q[1]);
            float m2 = __half2float(q[2]);
            float m3 = __half2float(q[3]);
            float rt = __half2float(q[4]);
            float wl = wp[rr * 3], wc = wp[rr * 3 + 1], wr = wp[rr * 3 + 2];
            a.x += l  * wl + m0 * wc + m1 * wr;
            a.y += m0 * wl + m1 * wc + m2 * wr;
            a.z += m1 * wl + m2 * wc + m3 * wr;
            a.w += m2 * wl + m3 * wc + rt * wr;
        }
        int pix = px * 64 + g * 4;
        sq_out[(pix + 0) * 36 + ch] = __float2half_rn(a.x);
        sq_out[(pix + 1) * 36 + ch] = __float2half_rn(a.y);
        sq_out[(pix + 2) * 36 + ch] = __float2half_rn(a.z);
        sq_out[(pix + 3) * 36 + ch] = __float2half_rn(a.w);
    }
    __syncthreads();

    float qv[DHEAD];
    {
        const __half2* qrow = reinterpret_cast<const __half2*>(&sq_out[tid * 36]);
#pragma unroll
        for (int d2 = 0; d2 < 16; d2++) {
            float2 f = __half22float2(qrow[d2]);
            qv[d2 * 2] = f.x; qv[d2 * 2 + 1] = f.y;
        }
    }
    float m = -1e30f;
#pragma unroll
    for (int d = 0; d < DHEAD; d++) m = fmaxf(m, qv[d]);
    float ssum = 0.f;
#pragma unroll
    for (int d = 0; d < DHEAD; d++) { qv[d] = __expf(qv[d] - m); ssum += qv[d]; }
    float qinv = SCALE / ssum;

    float o[DHEAD];
#pragma unroll
    for (int e = 0; e < DHEAD; e++) o[e] = 0.f;
#pragma unroll 8
    for (int d = 0; d < DHEAD; d++) {
        float qd = qv[d] * qinv;
#pragma unroll
        for (int e = 0; e < DHEAD; e++) o[e] += qd * cs[d][e];
    }

    int p = R0 * 64 + tid;
    __half* ob = out + ((size_t)b * NPIX + p) * DIM + h * DHEAD;
#pragma unroll
    for (int e8 = 0; e8 < DHEAD; e8 += 8) {
        __half2 hh[4];
#pragma unroll
        for (int j = 0; j < 4; j++) {
            float x0 = o[e8 + 2*j],     s0 = x0 / (1.f + __expf(-x0));
            float x1 = o[e8 + 2*j + 1], s1 = x1 / (1.f + __expf(-x1));
            hh[j] = __floats2half2_rn(s0, s1);
        }
        *reinterpret_cast<uint4*>(ob + e8) = *reinterpret_cast<uint4*>(hh);
    }
}

// =====================================================================
// 6. wo GEMM + fused channel LayerNorm -> d_out (proven)
// =====================================================================
#define WOK 32
#define WOLD (WOK + 8)
#define WO_PIPE_BYTES ((256 * WOLD + 64 * WOLD) * 2 * 2)
#define WO_EP_BYTES   (256 * 68 * 4)
#define WO_DYN (WO_EP_BYTES > WO_PIPE_BYTES ? WO_EP_BYTES : WO_PIPE_BYTES)

__global__ __launch_bounds__(512)
void gemm_wo_ln(const __half* __restrict__ A, const __half* __restrict__ B,
                const float* __restrict__ gout, float* __restrict__ out)
{
    extern __shared__ char dyn[];
    typedef __half AsT[256][WOLD];
    typedef __half BsT[64][WOLD];
    AsT* As = (AsT*)dyn;
    BsT* Bs = (BsT*)(dyn + 2 * 256 * WOLD * 2);
    float (*ep)[68] = (float (*)[68])dyn;

    __shared__ float red1[8][64], red2[8][64];
    __shared__ float smean[64], srstd[64];

    const int tid = threadIdx.x;
    const int bn = blockIdx.x * 64;
    const int z  = blockIdx.z;
    const __half* Bb = B + (size_t)z * NPIX * DIM;

    const int warp = tid >> 5;
    const int wm = (warp >> 1) * 32;
    const int wn = (warp & 1) * 32;

    const int ar  = tid >> 2;
    const int ac8 = (tid & 3) * 8;
    const __half* gA0 = &A[(size_t)ar * 256 + ac8];
    const __half* gA1 = &A[(size_t)(ar + 128) * 256 + ac8];
    const __half* gB = &Bb[(size_t)(bn + (tid >> 2)) * 256 + ac8];

    wmma::fragment<wmma::accumulator, 16, 16, 16, float> acc[2][2];
#pragma unroll
    for (int i = 0; i < 2; i++)
#pragma unroll
        for (int j = 0; j < 2; j++) wmma::fill_fragment(acc[i][j], 0.f);

    cp16s(&(*As)[ar][ac8],       gA0);
    cp16s(&(*As)[ar + 128][ac8], gA1);
    if (tid < 256) cp16s(&(*Bs)[tid >> 2][ac8], gB);
    CP_COMMIT();

    int buf = 0;
#pragma unroll 1
    for (int t = 0; t < 8; t++) {
        CP_WAIT0();
        __syncthreads();
        if (t < 7) {
            int k0 = (t + 1) * WOK;
            cp16s(&As[buf ^ 1][0][0] + (size_t)ar * WOLD + ac8,         gA0 + k0);
            cp16s(&As[buf ^ 1][0][0] + (size_t)(ar + 128) * WOLD + ac8, gA1 + k0);
            if (tid < 256)
                cp16s(&Bs[buf ^ 1][0][0] + (size_t)(tid >> 2) * WOLD + ac8, gB + k0);
            CP_COMMIT();
        }
#pragma unroll
        for (int kk = 0; kk < WOK; kk += 16) {
            wmma::fragment<wmma::matrix_a, 16, 16, 16, __half, wmma::row_major> af[2];
            wmma::fragment<wmma::matrix_b, 16, 16, 16, __half, wmma::col_major> bf[2];
#pragma unroll
            for (int i = 0; i < 2; i++)
                wmma::load_matrix_sync(af[i], &As[buf][0][0] + (size_t)(wm + i * 16) * WOLD + kk, WOLD);
#pragma unroll
            for (int j = 0; j < 2; j++)
                wmma::load_matrix_sync(bf[j], &Bs[buf][0][0] + (size_t)(wn + j * 16) * WOLD + kk, WOLD);
#pragma unroll
            for (int i = 0; i < 2; i++)
#pragma unroll
                for (int j = 0; j < 2; j++)
                    wmma::mma_sync(acc[i][j], af[i], bf[j], acc[i][j]);
        }
        buf ^= 1;
    }

    __syncthreads();
#pragma unroll
    for (int i = 0; i < 2; i++)
#pragma unroll
        for (int j = 0; j < 2; j++)
            wmma::store_matrix_sync(&ep[wm + i * 16][wn + j * 16], acc[i][j], 68,
                                    wmma::mem_row_major);
    __syncthreads();

    {
        int col = tid & 63, part = tid >> 6;
        float s = 0.f, ss = 0.f;
#pragma unroll 8
        for (int rI = part * 32; rI < part * 32 + 32; rI++) {
            float v = ep[rI][col];
            s += v; ss += v * v;
        }
        red1[part][col] = s;
        red2[part][col] = ss;
    }
    __syncthreads();
    if (tid < 64) {
        float s = 0.f, ss = 0.f;
#pragma unroll
        for (int pI = 0; pI < 8; pI++) { s += red1[pI][tid]; ss += red2[pI][tid]; }
        float mean = s * (1.f / 256.f);
        float var  = ss * (1.f / 256.f) - mean * mean;
        smean[tid] = mean;
        srstd[tid] = rsqrtf(var + EPS);
    }
    __syncthreads();

    float* ob = out + (size_t)z * DIM * NPIX + bn;
    for (int idx = tid; idx < 256 * 64; idx += 512) {
        int c = idx >> 6, p = idx & 63;
        ob[(size_t)c * NPIX + p] = (ep[c][p] - smean[p]) * srstd[p] * __ldg(&gout[c]);
    }
}

// =====================================================================
// launch
// =====================================================================
extern "C" void kernel_launch(void* const* d_in, const int* in_sizes, int n_in,
                              void* d_out, int out_size)
{
    const float* fmap   = (const float*)d_in[0];
    const float* gn     = (const float*)d_in[1];
    const float* wq1    = (const float*)d_in[2];
    const float* wq_dw  = (const float*)d_in[3];
    const float* wk1    = (const float*)d_in[4];
    const float* wk_dw  = (const float*)d_in[5];
    const float* wv1    = (const float*)d_in[6];
    const float* wv_dw  = (const float*)d_in[7];
    const float* wo     = (const float*)d_in[8];
    const float* gout   = (const float*)d_in[9];
    float* out = (float*)d_out;

    __half *xnh, *qkvh, *kvh, *wqkv, *wo2;
    float *ctxp;
    cudaGetSymbolAddress((void**)&xnh,  g_xnh);
    cudaGetSymbolAddress((void**)&qkvh, g_qkv);
    cudaGetSymbolAddress((void**)&kvh,  g_kv);
    cudaGetSymbolAddress((void**)&ctxp, g_ctxp);
    cudaGetSymbolAddress((void**)&wqkv, g_wqkv);
    cudaGetSymbolAddress((void**)&wo2,  g_wo2);

    cudaFuncSetAttribute(gemm_qkv,   cudaFuncAttributeMaxDynamicSharedMemorySize, QKV_DYN);
    cudaFuncSetAttribute(gemm_wo_ln, cudaFuncAttributeMaxDynamicSharedMemorySize, WO_DYN);
    cudaFuncSetAttribute(attn_fused, cudaFuncAttributeMaxDynamicSharedMemorySize, AF_DYN);

    // 0a/0b. weights -> fp16 (split so gemm_qkv is launch #4 for ncu)
    round_weights_qkv<<<768, 256>>>(wq1, wk1, wv1);

    // 1. channel LN -> pixel-major fp16
    ln_to_pix<<<256, 256>>>(fmap, gn, xnh);

    round_weights_wo<<<256, 256>>>(wo);

    // 2. fused QKV 1x1 conv (3-stage pipeline), fp16 outputs
    gemm_qkv<<<dim3(NPIX / BN, 768 / BM, BATCH), 512, QKV_DYN>>>(wqkv, xnh, qkvh);

    // 3. depthwise 3x3 k,v (fp16 end-to-end, fused k sequence-softmax)
    dwconv_kv<<<BATCH * 512, 256>>>(qkvh, wk_dw, wv_dw, kvh);

    // 4. partial ctx = k^T v (fp16 in, 4 pixel slices)
    ctx_part<<<dim3(BATCH * HEADS, 4), 256>>>(kvh, ctxp);

    // 5. fused q dwconv + softmax + q@ctx + SiLU -> pixel-major fp16
    attn_fused<<<2048, 256, AF_DYN>>>(qkvh, wq_dw, ctxp, xnh);

    // 6. wo GEMM + fused final LayerNorm -> d_out
    gemm_wo_ln<<<dim3(NPIX / 64, 1, BATCH), 512, WO_DYN>>>(wo2, xnh, gout, out);
}

// round 14
// speedup vs baseline: 1.0318x; 1.0318x over previous
#include <cuda_runtime.h>
#include <cuda_fp16.h>
#include <mma.h>
#include <cstdint>

using namespace nvcuda;

// ---------------- problem constants ----------------
#define BATCH   16
#define DIM     256
#define HEADS   8
#define DHEAD   32
#define NPIX    4096
#define SCALE   0.17677669529663687f
#define EPS     1e-5f

// ---------------- scratch ----------------
__device__ __half g_xnh [(size_t)BATCH * NPIX * DIM];
__device__ __half g_qkv [(size_t)BATCH * 768 * NPIX];
__device__ __half g_kv  [(size_t)BATCH * 512 * NPIX];
__device__ float  g_ctxp[(size_t)BATCH * HEADS * 4 * DHEAD * DHEAD];
__device__ __half g_wqkv[768 * 256];
__device__ __half g_wo2 [256 * 256];

__device__ __forceinline__ void cp16s(void* dst, const void* src) {
    unsigned d = (unsigned)__cvta_generic_to_shared(dst);
    asm volatile("cp.async.cg.shared.global [%0], [%1], 16;\n" :: "r"(d), "l"(src));
}
#define CP_COMMIT()  asm volatile("cp.async.commit_group;\n" ::: "memory")
#define CP_WAIT0()   asm volatile("cp.async.wait_group 0;\n" ::: "memory")
#define CP_WAIT1()   asm volatile("cp.async.wait_group 1;\n" ::: "memory")

// =====================================================================
// 0a/0b. weights -> fp16 (split so gemm_qkv stays launch #4 for ncu)
// =====================================================================
__global__ __launch_bounds__(256)
void round_weights_qkv(const float* __restrict__ wq, const float* __restrict__ wk,
                       const float* __restrict__ wv)
{
    int i = blockIdx.x * 256 + threadIdx.x;
    if (i < 65536)       g_wqkv[i] = __float2half_rn(wq[i]);
    else if (i < 131072) g_wqkv[i] = __float2half_rn(wk[i - 65536]);
    else                 g_wqkv[i] = __float2half_rn(wv[i - 131072]);
}

__global__ __launch_bounds__(256)
void round_weights_wo(const float* __restrict__ wo)
{
    int i = blockIdx.x * 256 + threadIdx.x;
    g_wo2[i] = __float2half_rn(wo[i]);
}

// =====================================================================
// 1. channel LayerNorm: channel-major fp32 in -> pixel-major fp16 out
// =====================================================================
__global__ __launch_bounds__(256)
void ln_to_pix(const float* __restrict__ in, const float* __restrict__ g,
               __half* __restrict__ out)
{
    int idx = blockIdx.x * 256 + threadIdx.x;
    int b = idx >> 12, p = idx & 4095;
    const float* base = in + (size_t)b * DIM * NPIX + p;

    float s = 0.f, ss = 0.f;
#pragma unroll 8
    for (int c = 0; c < DIM; c++) {
        float v = base[(size_t)c * NPIX];
        s += v; ss += v * v;
    }
    float mean = s * (1.f / DIM);
    float var  = ss * (1.f / DIM) - mean * mean;
    float rstd = rsqrtf(var + EPS);

    __half* orow = out + ((size_t)b * NPIX + p) * DIM;
#pragma unroll 4
    for (int c = 0; c < DIM; c += 8) {
        __half2 h[4];
#pragma unroll
        for (int j = 0; j < 4; j++) {
            float a = (base[(size_t)(c + 2*j)     * NPIX] - mean) * rstd * __ldg(&g[c + 2*j]);
            float bb= (base[(size_t)(c + 2*j + 1) * NPIX] - mean) * rstd * __ldg(&g[c + 2*j + 1]);
            h[j] = __floats2half2_rn(a, bb);
        }
        *reinterpret_cast<uint4*>(orow + c) = *reinterpret_cast<uint4*>(h);
    }
}

// =====================================================================
// 2. QKV fp16 WMMA GEMM: 256 threads, 8 warps, 64x32 warp tiles (4x2
//    frags), 3-stage cp.async, fp16 staging epilogue.
// =====================================================================
#define BM 128
#define BN 128
#define BKH 32
#define LDH (BKH + 8)
#define STG_LD 20
#define QKV_DYN (3 * (BM * LDH + BN * LDH) * 2)   /* 61440 B */

__global__ __launch_bounds__(256, 2)
void gemm_qkv(const __half* __restrict__ A, const __half* __restrict__ B,
              __half* __restrict__ C)
{
    extern __shared__ char gsm[];
    typedef __half AsT[BM][LDH];
    typedef __half BsT[BN][LDH];
    AsT* As = reinterpret_cast<AsT*>(gsm);                          // As[3]
    BsT* Bs = reinterpret_cast<BsT*>(gsm + 3 * BM * LDH * 2);       // Bs[3]

    const int tid = threadIdx.x;
    const int bm = blockIdx.y * BM;
    const int bn = blockIdx.x * BN;
    const int z  = blockIdx.z;
    const __half* Bb = B + (size_t)z * NPIX * DIM;

    const int warp = tid >> 5;
    const int wm = (warp >> 2) * 64;        // 0 or 64
    const int wn = (warp & 3) * 32;         // 0..96

    const int row  = tid >> 2;              // 0..63
    const int col8 = (tid & 3) * 8;
    const __half* gA0 = &A[(size_t)(bm + row) * 256 + col8];
    const __half* gA1 = &A[(size_t)(bm + row + 64) * 256 + col8];
    const __half* gB0 = &Bb[(size_t)(bn + row) * 256 + col8];
    const __half* gB1 = &Bb[(size_t)(bn + row + 64) * 256 + col8];

    wmma::fragment<wmma::accumulator, 16, 16, 16, float> acc[4][2];
#pragma unroll
    for (int i = 0; i < 4; i++)
#pragma unroll
        for (int j = 0; j < 2; j++) wmma::fill_fragment(acc[i][j], 0.f);

    // prologue: chunks 0,1 into stages 0,1
#pragma unroll
    for (int c = 0; c < 2; c++) {
        cp16s(&As[c][row][col8],      gA0 + c * BKH);
        cp16s(&As[c][row + 64][col8], gA1 + c * BKH);
        cp16s(&Bs[c][row][col8],      gB0 + c * BKH);
        cp16s(&Bs[c][row + 64][col8], gB1 + c * BKH);
        CP_COMMIT();
    }

#pragma unroll 1
    for (int t = 0; t < 8; t++) {
        if (t < 7) { CP_WAIT1(); } else { CP_WAIT0(); }
        __syncthreads();
        if (t + 2 < 8) {
            int s = (t + 2) % 3;
            int k0 = (t + 2) * BKH;
            cp16s(&As[s][row][col8],      gA0 + k0);
            cp16s(&As[s][row + 64][col8], gA1 + k0);
            cp16s(&Bs[s][row][col8],      gB0 + k0);
            cp16s(&Bs[s][row + 64][col8], gB1 + k0);
            CP_COMMIT();
        }
        int cs_ = t % 3;
#pragma unroll
        for (int kk = 0; kk < BKH; kk += 16) {
            wmma::fragment<wmma::matrix_a, 16, 16, 16, __half, wmma::row_major> af[4];
            wmma::fragment<wmma::matrix_b, 16, 16, 16, __half, wmma::col_major> bf[2];
#pragma unroll
            for (int i = 0; i < 4; i++)
                wmma::load_matrix_sync(af[i], &As[cs_][wm + i * 16][kk], LDH);
#pragma unroll
            for (int j = 0; j < 2; j++)
                wmma::load_matrix_sync(bf[j], &Bs[cs_][wn + j * 16][kk], LDH);
#pragma unroll
            for (int i = 0; i < 4; i++)
#pragma unroll
                for (int j = 0; j < 2; j++)
                    wmma::mma_sync(acc[i][j], af[i], bf[j], acc[i][j]);
        }
    }

    // fp16 epilogue via per-warp staging (reuse pipeline smem)
    __syncthreads();
    float* stg = reinterpret_cast<float*>(gsm) + warp * 16 * STG_LD;
    __half* Ch = C + (size_t)z * 768 * NPIX + (size_t)bm * NPIX;
    const int lane = tid & 31;
    const int r  = lane >> 1;
    const int c8 = (lane & 1) * 8;
#pragma unroll
    for (int i = 0; i < 4; i++)
#pragma unroll
        for (int j = 0; j < 2; j++) {
            wmma::store_matrix_sync(stg, acc[i][j], STG_LD, wmma::mem_row_major);
            __syncwarp();
            const float* src = stg + r * STG_LD + c8;
            __half2 hh[4];
#pragma unroll
            for (int q = 0; q < 4; q++)
                hh[q] = __floats2half2_rn(src[2*q], src[2*q + 1]);
            __half* dst = Ch + (size_t)(wm + i * 16 + r) * NPIX
                             + bn + wn + j * 16 + c8;
            *reinterpret_cast<uint4*>(dst) = *reinterpret_cast<uint4*>(hh);
            __syncwarp();
        }
}

// =====================================================================
// 3. depthwise 3x3 for k,v — fp16 end-to-end (proven round 12).
// =====================================================================
#define KVLD 80

__global__ __launch_bounds__(256)
void dwconv_kv(const __half* __restrict__ qkv, const float* __restrict__ wk,
               const float* __restrict__ wv, __half* __restrict__ kvout)
{
    __shared__ __half s[66 * KVLD];
    __shared__ float red[8];
    int bc = blockIdx.x;
    int b = bc >> 9;
    int ch = bc & 511;
    bool is_k = ch < 256;
    const float* w9 = is_k ? wk + ch * 9 : wv + (ch - 256) * 9;
    float w0 = w9[0], w1 = w9[1], w2 = w9[2], w3 = w9[3], w4 = w9[4],
          w5 = w9[5], w6 = w9[6], w7 = w9[7], w8 = w9[8];

    const __half* ip = qkv + ((size_t)b * 768 + 256 + ch) * NPIX;
    __half*       op = kvout + ((size_t)b * 512 + ch) * NPIX;

    int tid = threadIdx.x;
    if (tid < 66) {
        s[7 + tid] = __ushort_as_half(0);
        s[65 * KVLD + 7 + tid] = __ushort_as_half(0);
    }
    if (tid < 64) {
        s[(tid + 1) * KVLD + 7]  = __ushort_as_half(0);
        s[(tid + 1) * KVLD + 72] = __ushort_as_half(0);
    }
    __syncthreads();

    const uint2* ip2 = reinterpret_cast<const uint2*>(ip);
#pragma unroll
    for (int t = 0; t < 4; t++) {
        int i = tid + t * 256;
        int x = i >> 4, y4 = (i & 15) << 2;
        *reinterpret_cast<uint2*>(&s[(x + 1) * KVLD + 8 + y4]) = ip2[i];
    }
    __syncthreads();

    float4 r4[4];
#pragma unroll
    for (int t = 0; t < 4; t++) {
        int i = tid + t * 256;
        int x = i >> 4, y4 = (i & 15) << 2;
        const __half* p = &s[(x + 1) * KVLD + 8 + y4];
        float4 a = make_float4(0.f, 0.f, 0.f, 0.f);
#pragma unroll
        for (int rr = 0; rr < 3; rr++) {
            const __half* q = p + (rr - 1) * KVLD;
            float l  = __half2float(q[-1]);
            float m0 = __half2float(q[0]);
            float m1 = __half2float(q[1]);
            float m2 = __half2float(q[2]);
            float m3 = __half2float(q[3]);
            float rt = __half2float(q[4]);
            float wl = (rr == 0) ? w0 : (rr == 1) ? w3 : w6;
            float wc = (rr == 0) ? w1 : (rr == 1) ? w4 : w7;
            float wr = (rr == 0) ? w2 : (rr == 1) ? w5 : w8;
            a.x += l  * wl + m0 * wc + m1 * wr;
            a.y += m0 * wl + m1 * wc + m2 * wr;
            a.z += m1 * wl + m2 * wc + m3 * wr;
            a.w += m2 * wl + m3 * wc + rt * wr;
        }
        r4[t] = a;
    }

    uint2* op2 = reinterpret_cast<uint2*>(op);
    if (!is_k) {
#pragma unroll
        for (int t = 0; t < 4; t++) {
            uint2 raw;
            __half2* hp = reinterpret_cast<__half2*>(&raw);
            hp[0] = __floats2half2_rn(r4[t].x, r4[t].y);
            hp[1] = __floats2half2_rn(r4[t].z, r4[t].w);
            op2[tid + t * 256] = raw;
        }
        return;
    }

    float m = -1e30f;
#pragma unroll
    for (int t = 0; t < 4; t++)
        m = fmaxf(m, fmaxf(fmaxf(r4[t].x, r4[t].y), fmaxf(r4[t].z, r4[t].w)));
#pragma unroll
    for (int o = 16; o; o >>= 1) m = fmaxf(m, __shfl_xor_sync(~0u, m, o));
    if ((tid & 31) == 0) red[tid >> 5] = m;
    __syncthreads();
    m = red[0];
#pragma unroll
    for (int w = 1; w < 8; w++) m = fmaxf(m, red[w]);

    float ssum = 0.f;
#pragma unroll
    for (int t = 0; t < 4; t++) {
        r4[t].x = __expf(r4[t].x - m); ssum += r4[t].x;
        r4[t].y = __expf(r4[t].y - m); ssum += r4[t].y;
        r4[t].z = __expf(r4[t].z - m); ssum += r4[t].z;
        r4[t].w = __expf(r4[t].w - m); ssum += r4[t].w;
    }
#pragma unroll
    for (int o = 16; o; o >>= 1) ssum += __shfl_xor_sync(~0u, ssum, o);
    __syncthreads();
    if ((tid & 31) == 0) red[tid >> 5] = ssum;
    __syncthreads();
    ssum = 0.f;
#pragma unroll
    for (int w = 0; w < 8; w++) ssum += red[w];

    float inv = 1.f / ssum;
#pragma unroll
    for (int t = 0; t < 4; t++) {
        uint2 raw;
        __half2* hp = reinterpret_cast<__half2*>(&raw);
        hp[0] = __floats2half2_rn(r4[t].x * inv, r4[t].y * inv);
        hp[1] = __floats2half2_rn(r4[t].z * inv, r4[t].w * inv);
        op2[tid + t * 256] = raw;
    }
}

// =====================================================================
// 4. partial ctx: ctxp[bh][s][d][e] = sum_{p in slice} k*v (fp16 in)
// =====================================================================
__global__ __launch_bounds__(256)
void ctx_part(const __half* __restrict__ kv, float* __restrict__ ctxp)
{
    __shared__ float sh[8448];
    float* ksT = sh;
    float* vsT = sh + 4224;

    int bh = blockIdx.x;
    int sl = blockIdx.y;
    int b = bh >> 3, h = bh & 7;
    const __half* kb = kv + ((size_t)b * 512 + h * DHEAD) * NPIX;
    const __half* vb = kv + ((size_t)b * 512 + 256 + h * DHEAD) * NPIX;

    int tid = threadIdx.x;
    int pg = tid >> 6;
    int t  = tid & 63;
    int d0 = (t >> 3) * 4;
    int e0 = (t & 7) * 4;

    float acc[16];
#pragma unroll
    for (int i = 0; i < 16; i++) acc[i] = 0.f;

    int base = sl * 1024;
    for (int c0 = base; c0 < base + 1024; c0 += 128) {
        __syncthreads();
        for (int i = tid; i < 2048; i += 256) {
            int d = i >> 6, p2 = (i & 63) * 2;
            __half2 kk = *reinterpret_cast<const __half2*>(&kb[(size_t)d * NPIX + c0 + p2]);
            __half2 vv = *reinterpret_cast<const __half2*>(&vb[(size_t)d * NPIX + c0 + p2]);
            float2 kf = __half22float2(kk);
            float2 vf = __half22float2(vv);
            ksT[(p2 + 0) * 33 + d] = kf.x;
            ksT[(p2 + 1) * 33 + d] = kf.y;
            vsT[(p2 + 0) * 33 + d] = vf.x;
            vsT[(p2 + 1) * 33 + d] = vf.y;
        }
        __syncthreads();
        int pbeg = pg * 32;
#pragma unroll 4
        for (int pp = pbeg; pp < pbeg + 32; pp++) {
            float kk[4], vv[4];
#pragma unroll
            for (int i = 0; i < 4; i++) kk[i] = ksT[pp * 33 + d0 + i];
#pragma unroll
            for (int j = 0; j < 4; j++) vv[j] = vsT[pp * 33 + e0 + j];
#pragma unroll
            for (int i = 0; i < 4; i++)
#pragma unroll
                for (int j = 0; j < 4; j++) acc[i * 4 + j] += kk[i] * vv[j];
        }
    }
    __syncthreads();

    float* red = sh;
#pragma unroll
    for (int i = 0; i < 4; i++)
#pragma unroll
        for (int j = 0; j < 4; j++)
            red[pg * 1024 + (d0 + i) * 32 + (e0 + j)] = acc[i * 4 + j];
    __syncthreads();

    float* cout = ctxp + ((size_t)bh * 4 + sl) * 1024;
    for (int i = tid; i < 1024; i += 256)
        cout[i] = red[i] + red[1024 + i] + red[2048 + i] + red[3072 + i];
}

// =====================================================================
// 5. FUSED q path: dwconv3x3(q fp16) + feature-softmax + q@ctx + SiLU.
// =====================================================================
#define AF_SQIN_H  (32 * 6 * 80)
#define AF_SQOUT_H (256 * 36)
#define AF_DYN   ((AF_SQIN_H + AF_SQOUT_H) * 2)

__global__ __launch_bounds__(256)
void attn_fused(const __half* __restrict__ qkv, const float* __restrict__ wqdw,
                const float* __restrict__ ctxp, __half* __restrict__ out)
{
    extern __shared__ __half afsm[];
    __half* sq_in  = afsm;
    __half* sq_out = afsm + AF_SQIN_H;
    __shared__ float cs[DHEAD][DHEAD + 1];
    __shared__ float wsm[32][9];

    int blk = blockIdx.x;
    int pt = blk & 15;
    int bh = blk >> 4;
    int b = bh >> 3, h = bh & 7;
    int R0 = pt * 4;
    int tid = threadIdx.x;

    for (int i = tid; i < 288; i += 256)
        wsm[i / 9][i % 9] = wqdw[h * 288 + i];

    const uint2* qin2 = reinterpret_cast<const uint2*>(
        qkv + ((size_t)b * 768 + h * 32) * NPIX);
#pragma unroll
    for (int j = 0; j < 12; j++) {
        int i = tid + j * 256;
        int chl = i / 96;
        int rem = i - chl * 96;
        int rr = rem >> 4, g = rem & 15;
        int x = R0 - 1 + rr;
        uint2 raw = make_uint2(0u, 0u);
        if (x >= 0 && x < 64)
            raw = qin2[(size_t)chl * 1024 + x * 16 + g];
        *reinterpret_cast<uint2*>(&sq_in[(chl * 6 + rr) * 80 + 8 + g * 4]) = raw;
    }
    if (tid < 192) {
        sq_in[tid * 80 + 7]  = __ushort_as_half(0);
        sq_in[tid * 80 + 72] = __ushort_as_half(0);
    }

    const float* cbase = ctxp + (size_t)bh * 4096;
    for (int i = tid; i < 1024; i += 256)
        cs[i >> 5][i & 31] = cbase[i] + cbase[1024 + i] + cbase[2048 + i] + cbase[3072 + i];
    __syncthreads();

#pragma unroll
    for (int t = 0; t < 8; t++) {
        int w = tid + t * 256;
        int ch = w >> 6;
        int rem = w & 63;
        int px = rem >> 4, g = rem & 15;
        const float* wp = wsm[ch];
        float4 a = make_float4(0.f, 0.f, 0.f, 0.f);
#pragma unroll
        for (int rr = 0; rr < 3; rr++) {
            const __half* q = &sq_in[(ch * 6 + px + rr) * 80 + 8 + g * 4];
            float l  = __half2float(q[-1]);
            float m0 = __half2float(q[0]);
            float m1 = __half2float(q[1]);
            float m2 = __half2float(q[2]);
            float m3 = __half2float(q[3]);
            float rt = __half2float(q[4]);
            float wl = wp[rr * 3], wc = wp[rr * 3 + 1], wr = wp[rr * 3 + 2];
            a.x += l  * wl + m0 * wc + m1 * wr;
            a.y += m0 * wl + m1 * wc + m2 * wr;
            a.z += m1 * wl + m2 * wc + m3 * wr;
            a.w += m2 * wl + m3 * wc + rt * wr;
        }
        int pix = px * 64 + g * 4;
        sq_out[(pix + 0) * 36 + ch] = __float2half_rn(a.x);
        sq_out[(pix + 1) * 36 + ch] = __float2half_rn(a.y);
        sq_out[(pix + 2) * 36 + ch] = __float2half_rn(a.z);
        sq_out[(pix + 3) * 36 + ch] = __float2half_rn(a.w);
    }
    __syncthreads();

    float qv[DHEAD];
    {
        const __half2* qrow = reinterpret_cast<const __half2*>(&sq_out[tid * 36]);
#pragma unroll
        for (int d2 = 0; d2 < 16; d2++) {
            float2 f = __half22float2(qrow[d2]);
            qv[d2 * 2] = f.x; qv[d2 * 2 + 1] = f.y;
        }
    }
    float m = -1e30f;
#pragma unroll
    for (int d = 0; d < DHEAD; d++) m = fmaxf(m, qv[d]);
    float ssum = 0.f;
#pragma unroll
    for (int d = 0; d < DHEAD; d++) { qv[d] = __expf(qv[d] - m); ssum += qv[d]; }
    float qinv = SCALE / ssum;

    float o[DHEAD];
#pragma unroll
    for (int e = 0; e < DHEAD; e++) o[e] = 0.f;
#pragma unroll 8
    for (int d = 0; d < DHEAD; d++) {
        float qd = qv[d] * qinv;
#pragma unroll
        for (int e = 0; e < DHEAD; e++) o[e] += qd * cs[d][e];
    }

    int p = R0 * 64 + tid;
    __half* ob = out + ((size_t)b * NPIX + p) * DIM + h * DHEAD;
#pragma unroll
    for (int e8 = 0; e8 < DHEAD; e8 += 8) {
        __half2 hh[4];
#pragma unroll
        for (int j = 0; j < 4; j++) {
            float x0 = o[e8 + 2*j],     s0 = x0 / (1.f + __expf(-x0));
            float x1 = o[e8 + 2*j + 1], s1 = x1 / (1.f + __expf(-x1));
            hh[j] = __floats2half2_rn(s0, s1);
        }
        *reinterpret_cast<uint4*>(ob + e8) = *reinterpret_cast<uint4*>(hh);
    }
}

// =====================================================================
// 6. wo GEMM + fused channel LayerNorm -> d_out (proven)
// =====================================================================
#define WOK 32
#define WOLD (WOK + 8)
#define WO_PIPE_BYTES ((256 * WOLD + 64 * WOLD) * 2 * 2)
#define WO_EP_BYTES   (256 * 68 * 4)
#define WO_DYN (WO_EP_BYTES > WO_PIPE_BYTES ? WO_EP_BYTES : WO_PIPE_BYTES)

__global__ __launch_bounds__(512)
void gemm_wo_ln(const __half* __restrict__ A, const __half* __restrict__ B,
                const float* __restrict__ gout, float* __restrict__ out)
{
    extern __shared__ char dyn[];
    typedef __half AsT[256][WOLD];
    typedef __half BsT[64][WOLD];
    AsT* As = (AsT*)dyn;
    BsT* Bs = (BsT*)(dyn + 2 * 256 * WOLD * 2);
    float (*ep)[68] = (float (*)[68])dyn;

    __shared__ float red1[8][64], red2[8][64];
    __shared__ float smean[64], srstd[64];

    const int tid = threadIdx.x;
    const int bn = blockIdx.x * 64;
    const int z  = blockIdx.z;
    const __half* Bb = B + (size_t)z * NPIX * DIM;

    const int warp = tid >> 5;
    const int wm = (warp >> 1) * 32;
    const int wn = (warp & 1) * 32;

    const int ar  = tid >> 2;
    const int ac8 = (tid & 3) * 8;
    const __half* gA0 = &A[(size_t)ar * 256 + ac8];
    const __half* gA1 = &A[(size_t)(ar + 128) * 256 + ac8];
    const __half* gB = &Bb[(size_t)(bn + (tid >> 2)) * 256 + ac8];

    wmma::fragment<wmma::accumulator, 16, 16, 16, float> acc[2][2];
#pragma unroll
    for (int i = 0; i < 2; i++)
#pragma unroll
        for (int j = 0; j < 2; j++) wmma::fill_fragment(acc[i][j], 0.f);

    cp16s(&(*As)[ar][ac8],       gA0);
    cp16s(&(*As)[ar + 128][ac8], gA1);
    if (tid < 256) cp16s(&(*Bs)[tid >> 2][ac8], gB);
    CP_COMMIT();

    int buf = 0;
#pragma unroll 1
    for (int t = 0; t < 8; t++) {
        CP_WAIT0();
        __syncthreads();
        if (t < 7) {
            int k0 = (t + 1) * WOK;
            cp16s(&As[buf ^ 1][0][0] + (size_t)ar * WOLD + ac8,         gA0 + k0);
            cp16s(&As[buf ^ 1][0][0] + (size_t)(ar + 128) * WOLD + ac8, gA1 + k0);
            if (tid < 256)
                cp16s(&Bs[buf ^ 1][0][0] + (size_t)(tid >> 2) * WOLD + ac8, gB + k0);
            CP_COMMIT();
        }
#pragma unroll
        for (int kk = 0; kk < WOK; kk += 16) {
            wmma::fragment<wmma::matrix_a, 16, 16, 16, __half, wmma::row_major> af[2];
            wmma::fragment<wmma::matrix_b, 16, 16, 16, __half, wmma::col_major> bf[2];
#pragma unroll
            for (int i = 0; i < 2; i++)
                wmma::load_matrix_sync(af[i], &As[buf][0][0] + (size_t)(wm + i * 16) * WOLD + kk, WOLD);
#pragma unroll
            for (int j = 0; j < 2; j++)
                wmma::load_matrix_sync(bf[j], &Bs[buf][0][0] + (size_t)(wn + j * 16) * WOLD + kk, WOLD);
#pragma unroll
            for (int i = 0; i < 2; i++)
#pragma unroll
                for (int j = 0; j < 2; j++)
                    wmma::mma_sync(acc[i][j], af[i], bf[j], acc[i][j]);
        }
        buf ^= 1;
    }

    __syncthreads();
#pragma unroll
    for (int i = 0; i < 2; i++)
#pragma unroll
        for (int j = 0; j < 2; j++)
            wmma::store_matrix_sync(&ep[wm + i * 16][wn + j * 16], acc[i][j], 68,
                                    wmma::mem_row_major);
    __syncthreads();

    {
        int col = tid & 63, part = tid >> 6;
        float s = 0.f, ss = 0.f;
#pragma unroll 8
        for (int rI = part * 32; rI < part * 32 + 32; rI++) {
            float v = ep[rI][col];
            s += v; ss += v * v;
        }
        red1[part][col] = s;
        red2[part][col] = ss;
    }
    __syncthreads();
    if (tid < 64) {
        float s = 0.f, ss = 0.f;
#pragma unroll
        for (int pI = 0; pI < 8; pI++) { s += red1[pI][tid]; ss += red2[pI][tid]; }
        float mean = s * (1.f / 256.f);
        float var  = ss * (1.f / 256.f) - mean * mean;
        smean[tid] = mean;
        srstd[tid] = rsqrtf(var + EPS);
    }
    __syncthreads();

    float* ob = out + (size_t)z * DIM * NPIX + bn;
    for (int idx = tid; idx < 256 * 64; idx += 512) {
        int c = idx >> 6, p = idx & 63;
        ob[(size_t)c * NPIX + p] = (ep[c][p] - smean[p]) * srstd[p] * __ldg(&gout[c]);
    }
}

// =====================================================================
// launch
// =====================================================================
extern "C" void kernel_launch(void* const* d_in, const int* in_sizes, int n_in,
                              void* d_out, int out_size)
{
    const float* fmap   = (const float*)d_in[0];
    const float* gn     = (const float*)d_in[1];
    const float* wq1    = (const float*)d_in[2];
    const float* wq_dw  = (const float*)d_in[3];
    const float* wk1    = (const float*)d_in[4];
    const float* wk_dw  = (const float*)d_in[5];
    const float* wv1    = (const float*)d_in[6];
    const float* wv_dw  = (const float*)d_in[7];
    const float* wo     = (const float*)d_in[8];
    const float* gout   = (const float*)d_in[9];
    float* out = (float*)d_out;

    __half *xnh, *qkvh, *kvh, *wqkv, *wo2;
    float *ctxp;
    cudaGetSymbolAddress((void**)&xnh,  g_xnh);
    cudaGetSymbolAddress((void**)&qkvh, g_qkv);
    cudaGetSymbolAddress((void**)&kvh,  g_kv);
    cudaGetSymbolAddress((void**)&ctxp, g_ctxp);
    cudaGetSymbolAddress((void**)&wqkv, g_wqkv);
    cudaGetSymbolAddress((void**)&wo2,  g_wo2);

    cudaFuncSetAttribute(gemm_qkv,   cudaFuncAttributeMaxDynamicSharedMemorySize, QKV_DYN);
    cudaFuncSetAttribute(gemm_wo_ln, cudaFuncAttributeMaxDynamicSharedMemorySize, WO_DYN);
    cudaFuncSetAttribute(attn_fused, cudaFuncAttributeMaxDynamicSharedMemorySize, AF_DYN);

    // 0a/0b. weights -> fp16 (split so gemm_qkv is launch #4 for ncu)
    round_weights_qkv<<<768, 256>>>(wq1, wk1, wv1);

    // 1. channel LN -> pixel-major fp16
    ln_to_pix<<<256, 256>>>(fmap, gn, xnh);

    round_weights_wo<<<256, 256>>>(wo);

    // 2. fused QKV 1x1 conv (64x32 warp tiles, 3-stage), fp16 outputs
    gemm_qkv<<<dim3(NPIX / BN, 768 / BM, BATCH), 256, QKV_DYN>>>(wqkv, xnh, qkvh);

    // 3. depthwise 3x3 k,v (fp16 end-to-end, fused k sequence-softmax)
    dwconv_kv<<<BATCH * 512, 256>>>(qkvh, wk_dw, wv_dw, kvh);

    // 4. partial ctx = k^T v (fp16 in, 4 pixel slices)
    ctx_part<<<dim3(BATCH * HEADS, 4), 256>>>(kvh, ctxp);

    // 5. fused q dwconv + softmax + q@ctx + SiLU -> pixel-major fp16
    attn_fused<<<2048, 256, AF_DYN>>>(qkvh, wq_dw, ctxp, xnh);

    // 6. wo GEMM + fused final LayerNorm -> d_out
    gemm_wo_ln<<<dim3(NPIX / 64, 1, BATCH), 512, WO_DYN>>>(wo2, xnh, gout, out);
}